// round 14
// baseline (speedup 1.0000x reference)
#include <cuda_runtime.h>
#include <cuda_fp16.h>
#include <math.h>
#include <cstdint>

#define B_ROWS 16384
#define H_DIM  512
#define K_DIM  512
#define N_OUT  1536   // 3*H

// fp16 copies of inputs (converted once per launch) + fp16 GEMM scratch.
__device__ __half g_xh[(size_t)B_ROWS * K_DIM];
__device__ __half g_hh[(size_t)B_ROWS * K_DIM];
__device__ __half g_wih[(size_t)N_OUT * K_DIM];
__device__ __half g_whh[(size_t)N_OUT * K_DIM];
__device__ __half g_xt[(size_t)B_ROWS * N_OUT];
__device__ __half g_ht[(size_t)B_ROWS * N_OUT];

// ─────────────── fp32 -> fp16 conversion (R12 version — measured 16.0 us) ───────────────
#define XH_N4 ((B_ROWS * K_DIM) / 4)   // 2097152
#define W_N4  ((N_OUT * K_DIM) / 4)    // 196608

__global__ __launch_bounds__(256) void convert_kernel(
    const float4* __restrict__ x, const float4* __restrict__ hx,
    const float4* __restrict__ Wi, const float4* __restrict__ Wh)
{
    const int sec = blockIdx.y;
    const float4* __restrict__ src;
    __half* dst;
    int n4;
    if      (sec == 0) { src = x;  dst = g_xh;  n4 = XH_N4; }
    else if (sec == 1) { src = hx; dst = g_hh;  n4 = XH_N4; }
    else if (sec == 2) { src = Wi; dst = g_wih; n4 = W_N4; }
    else               { src = Wh; dst = g_whh; n4 = W_N4; }

    uint2* __restrict__ d2 = (uint2*)dst;
    const int stride = gridDim.x * blockDim.x;
    for (int i = blockIdx.x * blockDim.x + threadIdx.x; i < n4; i += stride) {
        float4 v = src[i];
        __half2 lo = __floats2half2_rn(v.x, v.y);
        __half2 hi = __floats2half2_rn(v.z, v.w);
        uint2 o;
        o.x = *(uint32_t*)&lo;
        o.y = *(uint32_t*)&hi;
        d2[i] = o;
    }
}

// ─────────────── GEMM tiling: BK=32, 3-stage ring, prefetch distance 2 ───────────────
#define BM 128
#define BN 128
#define BK 32                            // halves per stage (64 B/row)
#define PITCH 40                         // halves; 80 B row stride = 20-bank step -> LDSM conflict-free
#define A_BYTES (BM * PITCH * 2)         // 10240
#define STAGE_BYTES (2 * A_BYTES)        // 20480
#define NSTAGE 3
#define SMEM_BYTES (NSTAGE * STAGE_BYTES)   // 61440 (x3 CTAs = 184320 <= 228KB)
#define KSTAGES (K_DIM / BK)             // 16
#define NTHREADS 128

__device__ __forceinline__ void cp_async16(uint32_t dst, const void* src) {
    asm volatile("cp.async.cg.shared.global [%0], [%1], 16;"
                 :: "r"(dst), "l"(src) : "memory");
}
#define CP_COMMIT() asm volatile("cp.async.commit_group;" ::: "memory")
#define CP_WAIT(n)  asm volatile("cp.async.wait_group %0;" :: "n"(n) : "memory")

__device__ __forceinline__ uint32_t smem_to_u32(const void* p) {
    uint32_t a;
    asm("{ .reg .u64 t; cvta.to.shared.u64 t, %1; cvt.u32.u64 %0, t; }"
        : "=r"(a) : "l"(p));
    return a;
}

__device__ __forceinline__ void ldsm_x4(uint32_t& r0, uint32_t& r1,
                                        uint32_t& r2, uint32_t& r3, uint32_t addr) {
    asm volatile("ldmatrix.sync.aligned.m8n8.x4.shared.b16 {%0,%1,%2,%3}, [%4];"
                 : "=r"(r0), "=r"(r1), "=r"(r2), "=r"(r3) : "r"(addr));
}

__device__ __forceinline__ void mma_f16(
    float& c0, float& c1, float& c2, float& c3,
    uint32_t a0, uint32_t a1, uint32_t a2, uint32_t a3,
    uint32_t b0, uint32_t b1)
{
    asm volatile(
        "mma.sync.aligned.m16n8k16.row.col.f32.f16.f16.f32 "
        "{%0,%1,%2,%3}, {%4,%5,%6,%7}, {%8,%9}, {%0,%1,%2,%3};"
        : "+f"(c0), "+f"(c1), "+f"(c2), "+f"(c3)
        : "r"(a0), "r"(a1), "r"(a2), "r"(a3), "r"(b0), "r"(b1));
}

// Fill one stage: A tile 128x32h + B tile 128x32h, 16B cp.async, [row][k] layout.
__device__ __forceinline__ void load_stage(
    uint32_t a_smem, uint32_t b_smem,
    const __half* __restrict__ A, const __half* __restrict__ W,
    int m0, int n0, int k0, int tid)
{
    // per operand: 128 rows x 4 chunks(16B=8h) = 512 chunks -> 4 per thread
#pragma unroll
    for (int i = 0; i < 4; i++) {
        int c   = i * NTHREADS + tid;
        int row = c >> 2;
        int ch  = c & 3;
        uint32_t off = (uint32_t)(row * PITCH + ch * 8) * 2u;
        cp_async16(a_smem + off, A + (size_t)(m0 + row) * K_DIM + k0 + ch * 8);
        cp_async16(b_smem + off, W + (size_t)(n0 + row) * K_DIM + k0 + ch * 8);
    }
}

// C[m,n] = sum_k A[m,k]*W[n,k] + bias[n], stored as fp16
__global__ __launch_bounds__(NTHREADS, 3) void gemm_tc_kernel(
    const float* __restrict__ bi, const float* __restrict__ bh)
{
    extern __shared__ float sm[];
    const int tid = threadIdx.x;
    const int which = blockIdx.z;
    const __half* __restrict__ A    = which ? g_hh  : g_xh;
    const __half* __restrict__ W    = which ? g_whh : g_wih;
    const float*  __restrict__ bias = which ? bh : bi;
    __half* __restrict__ C          = which ? g_ht : g_xt;
    const int m0 = blockIdx.y * BM;
    const int n0 = blockIdx.x * BN;

    const uint32_t sm32 = smem_to_u32(sm);

    const int wid  = tid >> 5;
    const int lane = tid & 31;
    const int wr   = wid >> 1;           // 0..1 -> 64-row band
    const int wc   = wid & 1;            // 0..1 -> 64-col band
    const int g    = lane >> 2;          // 0..7
    const int t    = lane & 3;           // 0..3

    // A (x4): lanes 0-15 -> 16 rows @ half-col 0; lanes 16-31 -> same rows @ half-col 8
    const uint32_t aOff = ((uint32_t)((wr * 64 + (lane & 15)) * PITCH
                                      + (lane >> 4) * 8)) * 2u;
    // B (x4, two 8-row n-bands per issue)
    const uint32_t bOff = ((uint32_t)((wc * 64 + ((lane >> 4) & 1) * 8 + (lane & 7)) * PITCH
                                      + ((lane >> 3) & 1) * 8)) * 2u + A_BYTES;

    float c[4][8][4];
#pragma unroll
    for (int mt = 0; mt < 4; mt++)
#pragma unroll
        for (int nt = 0; nt < 8; nt++)
#pragma unroll
            for (int r = 0; r < 4; r++) c[mt][nt][r] = 0.f;

    // Prologue: stages 0 and 1
    load_stage(sm32, sm32 + A_BYTES, A, W, m0, n0, 0, tid);
    CP_COMMIT();
    load_stage(sm32 + STAGE_BYTES, sm32 + STAGE_BYTES + A_BYTES, A, W, m0, n0, BK, tid);
    CP_COMMIT();

    for (int ks = 0; ks < KSTAGES; ks++) {
        if (ks < KSTAGES - 1) CP_WAIT(1); else CP_WAIT(0);
        __syncthreads();   // stage ks landed; all warps done with slot (ks-1)%3

        // Prefetch stage ks+2 into ring slot (ks+2)%3 == (ks-1)%3 (just freed)
        if (ks + 2 < KSTAGES) {
            const uint32_t sbase = sm32 + (uint32_t)((ks + 2) % NSTAGE) * STAGE_BYTES;
            load_stage(sbase, sbase + A_BYTES, A, W, m0, n0, (ks + 2) * BK, tid);
            CP_COMMIT();
        }

        const uint32_t buf = sm32 + (uint32_t)(ks % NSTAGE) * STAGE_BYTES;
        const uint32_t aBase = buf + aOff;
        const uint32_t bBase = buf + bOff;

#pragma unroll
        for (int k16 = 0; k16 < 2; k16++) {
            const uint32_t kOff = (uint32_t)(k16 * 16) * 2u;   // 16 halves per step
            uint32_t a[4][4];
#pragma unroll
            for (int mt = 0; mt < 4; mt++)
                ldsm_x4(a[mt][0], a[mt][1], a[mt][2], a[mt][3],
                        aBase + (uint32_t)(mt * 16 * PITCH) * 2u + kOff);
#pragma unroll
            for (int ntp = 0; ntp < 4; ntp++) {
                uint32_t b0, b1, b2, b3;   // b0,b1 = band 2*ntp; b2,b3 = band 2*ntp+1
                ldsm_x4(b0, b1, b2, b3,
                        bBase + (uint32_t)(ntp * 16 * PITCH) * 2u + kOff);
#pragma unroll
                for (int mt = 0; mt < 4; mt++) {
                    mma_f16(c[mt][2*ntp][0], c[mt][2*ntp][1],
                            c[mt][2*ntp][2], c[mt][2*ntp][3],
                            a[mt][0], a[mt][1], a[mt][2], a[mt][3], b0, b1);
                    mma_f16(c[mt][2*ntp+1][0], c[mt][2*ntp+1][1],
                            c[mt][2*ntp+1][2], c[mt][2*ntp+1][3],
                            a[mt][0], a[mt][1], a[mt][2], a[mt][3], b2, b3);
                }
            }
        }
    }

    // Store with bias as fp16. c0,c1 -> (row, col..col+1); c2,c3 -> (row+8, ...).
#pragma unroll
    for (int mt = 0; mt < 4; mt++) {
        const int row = m0 + wr * 64 + mt * 16 + g;
#pragma unroll
        for (int nt = 0; nt < 8; nt++) {
            const int col = n0 + wc * 64 + nt * 8 + 2 * t;
            const float b0 = __ldg(&bias[col]), b1 = __ldg(&bias[col + 1]);
            *(__half2*)&C[(size_t)row * N_OUT + col] =
                __floats2half2_rn(c[mt][nt][0] + b0, c[mt][nt][1] + b1);
            *(__half2*)&C[(size_t)(row + 8) * N_OUT + col] =
                __floats2half2_rn(c[mt][nt][2] + b0, c[mt][nt][3] + b1);
        }
    }
}

// ─────────────── LN/GRU epilogue (R12 version — measured ~45 us) ───────────────
__device__ __forceinline__ float fast_sigmoid(float x) {
    return 1.f / (1.f + __expf(-x));
}
__device__ __forceinline__ float fast_tanh(float x) {
    return 1.f - 2.f / (__expf(2.f * x) + 1.f);
}

__global__ __launch_bounds__(256) void epilogue_kernel(
    const float* __restrict__ hx, float* __restrict__ out)
{
    const int row = blockIdx.x;
    const int t = threadIdx.x;
    const __half2* __restrict__ xr = (const __half2*)g_xt + (size_t)row * (N_OUT / 2);
    const __half2* __restrict__ hr = (const __half2*)g_ht + (size_t)row * (N_OUT / 2);

    float2 xg01 = __half22float2(xr[t]);          // cols 2t, 2t+1        (r pre-acts)
    float2 xg23 = __half22float2(xr[256 + t]);    // cols 512+2t, 512+2t+1 (z pre-acts)
    float2 hg01 = __half22float2(hr[t]);
    float2 hg23 = __half22float2(hr[256 + t]);
    float2 xn01 = __half22float2(xr[512 + t]);    // cols 1024+2t, 1024+2t+1
    float2 hn01 = __half22float2(hr[512 + t]);

    float v[8];
    v[0] = xg01.x + xg01.y + xg23.x + xg23.y;
    v[1] = xg01.x*xg01.x + xg01.y*xg01.y + xg23.x*xg23.x + xg23.y*xg23.y;
    v[2] = hg01.x + hg01.y + hg23.x + hg23.y;
    v[3] = hg01.x*hg01.x + hg01.y*hg01.y + hg23.x*hg23.x + hg23.y*hg23.y;
    v[4] = xn01.x + xn01.y;
    v[5] = xn01.x*xn01.x + xn01.y*xn01.y;
    v[6] = hn01.x + hn01.y;
    v[7] = hn01.x*hn01.x + hn01.y*hn01.y;

    __shared__ float red[8][8];
    __shared__ float fin[8];
    const int lane = t & 31;
    const int warp = t >> 5;

#pragma unroll
    for (int s = 0; s < 8; s++) {
#pragma unroll
        for (int off = 16; off > 0; off >>= 1)
            v[s] += __shfl_down_sync(0xffffffffu, v[s], off);
    }
    if (lane == 0) {
#pragma unroll
        for (int s = 0; s < 8; s++) red[warp][s] = v[s];
    }
    __syncthreads();
    if (t < 8) {
        float s = 0.f;
#pragma unroll
        for (int w = 0; w < 8; w++) s += red[w][t];
        fin[t] = s;
    }
    __syncthreads();

    const float inv1024 = 1.f / 1024.f;
    const float inv512  = 1.f / 512.f;
    const float m_xg = fin[0] * inv1024;
    const float r_xg = rsqrtf(fin[1] * inv1024 - m_xg * m_xg + 1e-5f);
    const float m_hg = fin[2] * inv1024;
    const float r_hg = rsqrtf(fin[3] * inv1024 - m_hg * m_hg + 1e-5f);
    const float m_xn = fin[4] * inv512;
    const float r_xn = rsqrtf(fin[5] * inv512 - m_xn * m_xn + 1e-5f);
    const float m_hn = fin[6] * inv512;
    const float r_hn = rsqrtf(fin[7] * inv512 - m_hn * m_hn + 1e-5f);

    const float2 hv = *(const float2*)&hx[(size_t)row * H_DIM + 2 * t];

    float pre_r0 = (xg01.x - m_xg) * r_xg + (hg01.x - m_hg) * r_hg;
    float pre_z0 = (xg23.x - m_xg) * r_xg + (hg23.x - m_hg) * r_hg;
    float rg0 = fast_sigmoid(pre_r0);
    float zg0 = fast_sigmoid(pre_z0);
    float nt0 = fast_tanh((xn01.x - m_xn) * r_xn + rg0 * ((hn01.x - m_hn) * r_hn));
    float pre_r1 = (xg01.y - m_xg) * r_xg + (hg01.y - m_hg) * r_hg;
    float pre_z1 = (xg23.y - m_xg) * r_xg + (hg23.y - m_hg) * r_hg;
    float rg1 = fast_sigmoid(pre_r1);
    float zg1 = fast_sigmoid(pre_z1);
    float nt1 = fast_tanh((xn01.y - m_xn) * r_xn + rg1 * ((hn01.y - m_hn) * r_hn));

    float2 o;
    o.x = zg0 * hv.x + (1.f - zg0) * nt0;
    o.y = zg1 * hv.y + (1.f - zg1) * nt1;
    *(float2*)&out[(size_t)row * H_DIM + 2 * t] = o;
}

extern "C" void kernel_launch(void* const* d_in, const int* in_sizes, int n_in,
                              void* d_out, int out_size)
{
    const float* x     = (const float*)d_in[0];
    const float* hx    = (const float*)d_in[1];
    const float* W_i2h = (const float*)d_in[2];
    const float* b_i2h = (const float*)d_in[3];
    const float* W_h2h = (const float*)d_in[4];
    const float* b_h2h = (const float*)d_in[5];
    float* out = (float*)d_out;

    cudaFuncSetAttribute(gemm_tc_kernel,
                         cudaFuncAttributeMaxDynamicSharedMemorySize, SMEM_BYTES);

    dim3 cgrid(512, 4);
    convert_kernel<<<cgrid, 256>>>((const float4*)x, (const float4*)hx,
                                   (const float4*)W_i2h, (const float4*)W_h2h);

    dim3 grid(N_OUT / BN, B_ROWS / BM, 2);   // (12, 128, 2)
    gemm_tc_kernel<<<grid, NTHREADS, SMEM_BYTES>>>(b_i2h, b_h2h);
    epilogue_kernel<<<B_ROWS, 256>>>(hx, out);
}

// round 17
// speedup vs baseline: 1.1468x; 1.1468x over previous
#include <cuda_runtime.h>
#include <cuda_fp16.h>
#include <math.h>
#include <cstdint>

#define B_ROWS 16384
#define H_DIM  512
#define K_DIM  512
#define N_OUT  1536   // 3*H

// fp16 copies of inputs (converted once per launch) + fp16 GEMM scratch.
__device__ __half g_xh[(size_t)B_ROWS * K_DIM];
__device__ __half g_hh[(size_t)B_ROWS * K_DIM];
__device__ __half g_wih[(size_t)N_OUT * K_DIM];
__device__ __half g_whh[(size_t)N_OUT * K_DIM];
__device__ __half g_xt[(size_t)B_ROWS * N_OUT];
__device__ __half g_ht[(size_t)B_ROWS * N_OUT];

// ─────────────── fp32 -> fp16 conversion (R12 version — measured 16.0 us) ───────────────
#define XH_N4 ((B_ROWS * K_DIM) / 4)   // 2097152
#define W_N4  ((N_OUT * K_DIM) / 4)    // 196608

__global__ __launch_bounds__(256) void convert_kernel(
    const float4* __restrict__ x, const float4* __restrict__ hx,
    const float4* __restrict__ Wi, const float4* __restrict__ Wh)
{
    const int sec = blockIdx.y;
    const float4* __restrict__ src;
    __half* dst;
    int n4;
    if      (sec == 0) { src = x;  dst = g_xh;  n4 = XH_N4; }
    else if (sec == 1) { src = hx; dst = g_hh;  n4 = XH_N4; }
    else if (sec == 2) { src = Wi; dst = g_wih; n4 = W_N4; }
    else               { src = Wh; dst = g_whh; n4 = W_N4; }

    uint2* __restrict__ d2 = (uint2*)dst;
    const int stride = gridDim.x * blockDim.x;
    for (int i = blockIdx.x * blockDim.x + threadIdx.x; i < n4; i += stride) {
        float4 v = src[i];
        __half2 lo = __floats2half2_rn(v.x, v.y);
        __half2 hi = __floats2half2_rn(v.z, v.w);
        uint2 o;
        o.x = *(uint32_t*)&lo;
        o.y = *(uint32_t*)&hi;
        d2[i] = o;
    }
}

// ─────────────── GEMM tiling (exact R12 config — measured ~160 us pair) ───────────────
#define BM 128
#define BN 128
#define BK 64                            // halves per stage (128 B/row)
#define PITCH 72                         // halves; 144 B row stride -> LDSM conflict-free
#define A_BYTES (BM * PITCH * 2)         // 18432
#define STAGE_BYTES (2 * A_BYTES)        // 36864
#define NSTAGE 2
#define SMEM_BYTES (NSTAGE * STAGE_BYTES)   // 73728 (x3 CTAs <= 228KB)
#define KSTAGES (K_DIM / BK)             // 8
#define NTHREADS 128

__device__ __forceinline__ void cp_async16(uint32_t dst, const void* src) {
    asm volatile("cp.async.cg.shared.global [%0], [%1], 16;"
                 :: "r"(dst), "l"(src) : "memory");
}
#define CP_COMMIT() asm volatile("cp.async.commit_group;" ::: "memory")
#define CP_WAIT(n)  asm volatile("cp.async.wait_group %0;" :: "n"(n) : "memory")

__device__ __forceinline__ uint32_t smem_to_u32(const void* p) {
    uint32_t a;
    asm("{ .reg .u64 t; cvta.to.shared.u64 t, %1; cvt.u32.u64 %0, t; }"
        : "=r"(a) : "l"(p));
    return a;
}

__device__ __forceinline__ void ldsm_x4(uint32_t& r0, uint32_t& r1,
                                        uint32_t& r2, uint32_t& r3, uint32_t addr) {
    asm volatile("ldmatrix.sync.aligned.m8n8.x4.shared.b16 {%0,%1,%2,%3}, [%4];"
                 : "=r"(r0), "=r"(r1), "=r"(r2), "=r"(r3) : "r"(addr));
}

__device__ __forceinline__ void mma_f16(
    float& c0, float& c1, float& c2, float& c3,
    uint32_t a0, uint32_t a1, uint32_t a2, uint32_t a3,
    uint32_t b0, uint32_t b1)
{
    asm volatile(
        "mma.sync.aligned.m16n8k16.row.col.f32.f16.f16.f32 "
        "{%0,%1,%2,%3}, {%4,%5,%6,%7}, {%8,%9}, {%0,%1,%2,%3};"
        : "+f"(c0), "+f"(c1), "+f"(c2), "+f"(c3)
        : "r"(a0), "r"(a1), "r"(a2), "r"(a3), "r"(b0), "r"(b1));
}

__device__ __forceinline__ void load_stage(
    uint32_t a_smem, uint32_t b_smem,
    const __half* __restrict__ A, const __half* __restrict__ W,
    int m0, int n0, int k0, int tid)
{
#pragma unroll
    for (int i = 0; i < 8; i++) {
        int c   = i * NTHREADS + tid;
        int row = c >> 3;
        int ch  = c & 7;
        uint32_t off = (uint32_t)(row * PITCH + ch * 8) * 2u;
        cp_async16(a_smem + off, A + (size_t)(m0 + row) * K_DIM + k0 + ch * 8);
        cp_async16(b_smem + off, W + (size_t)(n0 + row) * K_DIM + k0 + ch * 8);
    }
}

__global__ __launch_bounds__(NTHREADS, 3) void gemm_tc_kernel(
    const float* __restrict__ bi, const float* __restrict__ bh)
{
    extern __shared__ float sm[];
    const int tid = threadIdx.x;
    const int which = blockIdx.z;
    const __half* __restrict__ A    = which ? g_hh  : g_xh;
    const __half* __restrict__ W    = which ? g_whh : g_wih;
    const float*  __restrict__ bias = which ? bh : bi;
    __half* __restrict__ C          = which ? g_ht : g_xt;
    const int m0 = blockIdx.y * BM;
    const int n0 = blockIdx.x * BN;

    const uint32_t sm32 = smem_to_u32(sm);

    const int wid  = tid >> 5;
    const int lane = tid & 31;
    const int wr   = wid >> 1;
    const int wc   = wid & 1;
    const int g    = lane >> 2;
    const int t    = lane & 3;

    const uint32_t aOff = ((uint32_t)((wr * 64 + (lane & 15)) * PITCH
                                      + (lane >> 4) * 8)) * 2u;
    const uint32_t bOff = ((uint32_t)((wc * 64 + ((lane >> 4) & 1) * 8 + (lane & 7)) * PITCH
                                      + ((lane >> 3) & 1) * 8)) * 2u + A_BYTES;

    float c[4][8][4];
#pragma unroll
    for (int mt = 0; mt < 4; mt++)
#pragma unroll
        for (int nt = 0; nt < 8; nt++)
#pragma unroll
            for (int r = 0; r < 4; r++) c[mt][nt][r] = 0.f;

    load_stage(sm32, sm32 + A_BYTES, A, W, m0, n0, 0, tid);
    CP_COMMIT();

    for (int ks = 0; ks < KSTAGES; ks++) {
        CP_WAIT(0);
        __syncthreads();

        if (ks + 1 < KSTAGES) {
            const uint32_t sbase = sm32 + (uint32_t)((ks + 1) & 1) * STAGE_BYTES;
            load_stage(sbase, sbase + A_BYTES, A, W, m0, n0, (ks + 1) * BK, tid);
            CP_COMMIT();
        }

        const uint32_t buf = sm32 + (uint32_t)(ks & 1) * STAGE_BYTES;
        const uint32_t aBase = buf + aOff;
        const uint32_t bBase = buf + bOff;

#pragma unroll
        for (int k16 = 0; k16 < 4; k16++) {
            const uint32_t kOff = (uint32_t)(k16 * 16) * 2u;
            uint32_t a[4][4];
#pragma unroll
            for (int mt = 0; mt < 4; mt++)
                ldsm_x4(a[mt][0], a[mt][1], a[mt][2], a[mt][3],
                        aBase + (uint32_t)(mt * 16 * PITCH) * 2u + kOff);
#pragma unroll
            for (int ntp = 0; ntp < 4; ntp++) {
                uint32_t b0, b1, b2, b3;
                ldsm_x4(b0, b1, b2, b3,
                        bBase + (uint32_t)(ntp * 16 * PITCH) * 2u + kOff);
#pragma unroll
                for (int mt = 0; mt < 4; mt++) {
                    mma_f16(c[mt][2*ntp][0], c[mt][2*ntp][1],
                            c[mt][2*ntp][2], c[mt][2*ntp][3],
                            a[mt][0], a[mt][1], a[mt][2], a[mt][3], b0, b1);
                    mma_f16(c[mt][2*ntp+1][0], c[mt][2*ntp+1][1],
                            c[mt][2*ntp+1][2], c[mt][2*ntp+1][3],
                            a[mt][0], a[mt][1], a[mt][2], a[mt][3], b2, b3);
                }
            }
        }
    }

#pragma unroll
    for (int mt = 0; mt < 4; mt++) {
        const int row = m0 + wr * 64 + mt * 16 + g;
#pragma unroll
        for (int nt = 0; nt < 8; nt++) {
            const int col = n0 + wc * 64 + nt * 8 + 2 * t;
            const float b0 = __ldg(&bias[col]), b1 = __ldg(&bias[col + 1]);
            *(__half2*)&C[(size_t)row * N_OUT + col] =
                __floats2half2_rn(c[mt][nt][0] + b0, c[mt][nt][1] + b1);
            *(__half2*)&C[(size_t)(row + 8) * N_OUT + col] =
                __floats2half2_rn(c[mt][nt][2] + b0, c[mt][nt][3] + b1);
        }
    }
}

// ─────────────── LN/GRU epilogue (tanh.approx for all transcendentals) ───────────────
__device__ __forceinline__ float tanh_fast(float x) {
    float y;
    asm("tanh.approx.f32 %0, %1;" : "=f"(y) : "f"(x));
    return y;
}
__device__ __forceinline__ float sigmoid_fast(float x) {
    return fmaf(tanh_fast(0.5f * x), 0.5f, 0.5f);
}

__global__ __launch_bounds__(256) void epilogue_kernel(
    const float* __restrict__ hx, float* __restrict__ out)
{
    const int row = blockIdx.x;
    const int t = threadIdx.x;
    const __half2* __restrict__ xr = (const __half2*)g_xt + (size_t)row * (N_OUT / 2);
    const __half2* __restrict__ hr = (const __half2*)g_ht + (size_t)row * (N_OUT / 2);

    float2 xg01 = __half22float2(xr[t]);          // cols 2t, 2t+1        (r pre-acts)
    float2 xg23 = __half22float2(xr[256 + t]);    // cols 512+2t, 512+2t+1 (z pre-acts)
    float2 hg01 = __half22float2(hr[t]);
    float2 hg23 = __half22float2(hr[256 + t]);
    float2 xn01 = __half22float2(xr[512 + t]);    // cols 1024+2t, 1024+2t+1
    float2 hn01 = __half22float2(hr[512 + t]);

    float v[8];
    v[0] = xg01.x + xg01.y + xg23.x + xg23.y;
    v[1] = xg01.x*xg01.x + xg01.y*xg01.y + xg23.x*xg23.x + xg23.y*xg23.y;
    v[2] = hg01.x + hg01.y + hg23.x + hg23.y;
    v[3] = hg01.x*hg01.x + hg01.y*hg01.y + hg23.x*hg23.x + hg23.y*hg23.y;
    v[4] = xn01.x + xn01.y;
    v[5] = xn01.x*xn01.x + xn01.y*xn01.y;
    v[6] = hn01.x + hn01.y;
    v[7] = hn01.x*hn01.x + hn01.y*hn01.y;

    __shared__ float red[8][8];
    __shared__ float fin[8];
    const int lane = t & 31;
    const int warp = t >> 5;

#pragma unroll
    for (int s = 0; s < 8; s++) {
#pragma unroll
        for (int off = 16; off > 0; off >>= 1)
            v[s] += __shfl_down_sync(0xffffffffu, v[s], off);
    }
    if (lane == 0) {
#pragma unroll
        for (int s = 0; s < 8; s++) red[warp][s] = v[s];
    }
    __syncthreads();
    if (t < 8) {
        float s = 0.f;
#pragma unroll
        for (int w = 0; w < 8; w++) s += red[w][t];
        fin[t] = s;
    }
    __syncthreads();

    const float inv1024 = 1.f / 1024.f;
    const float inv512  = 1.f / 512.f;
    const float m_xg = fin[0] * inv1024;
    const float r_xg = rsqrtf(fin[1] * inv1024 - m_xg * m_xg + 1e-5f);
    const float m_hg = fin[2] * inv1024;
    const float r_hg = rsqrtf(fin[3] * inv1024 - m_hg * m_hg + 1e-5f);
    const float m_xn = fin[4] * inv512;
    const float r_xn = rsqrtf(fin[5] * inv512 - m_xn * m_xn + 1e-5f);
    const float m_hn = fin[6] * inv512;
    const float r_hn = rsqrtf(fin[7] * inv512 - m_hn * m_hn + 1e-5f);

    const float2 hv = *(const float2*)&hx[(size_t)row * H_DIM + 2 * t];

    float pre_r0 = (xg01.x - m_xg) * r_xg + (hg01.x - m_hg) * r_hg;
    float pre_z0 = (xg23.x - m_xg) * r_xg + (hg23.x - m_hg) * r_hg;
    float rg0 = sigmoid_fast(pre_r0);
    float zg0 = sigmoid_fast(pre_z0);
    float nt0 = tanh_fast((xn01.x - m_xn) * r_xn + rg0 * ((hn01.x - m_hn) * r_hn));
    float pre_r1 = (xg01.y - m_xg) * r_xg + (hg01.y - m_hg) * r_hg;
    float pre_z1 = (xg23.y - m_xg) * r_xg + (hg23.y - m_hg) * r_hg;
    float rg1 = sigmoid_fast(pre_r1);
    float zg1 = sigmoid_fast(pre_z1);
    float nt1 = tanh_fast((xn01.y - m_xn) * r_xn + rg1 * ((hn01.y - m_hn) * r_hn));

    float2 o;
    o.x = zg0 * hv.x + (1.f - zg0) * nt0;
    o.y = zg1 * hv.y + (1.f - zg1) * nt1;
    *(float2*)&out[(size_t)row * H_DIM + 2 * t] = o;
}

extern "C" void kernel_launch(void* const* d_in, const int* in_sizes, int n_in,
                              void* d_out, int out_size)
{
    const float* x     = (const float*)d_in[0];
    const float* hx    = (const float*)d_in[1];
    const float* W_i2h = (const float*)d_in[2];
    const float* b_i2h = (const float*)d_in[3];
    const float* W_h2h = (const float*)d_in[4];
    const float* b_h2h = (const float*)d_in[5];
    float* out = (float*)d_out;

    cudaFuncSetAttribute(gemm_tc_kernel,
                         cudaFuncAttributeMaxDynamicSharedMemorySize, SMEM_BYTES);

    dim3 cgrid(512, 4);
    convert_kernel<<<cgrid, 256>>>((const float4*)x, (const float4*)hx,
                                   (const float4*)W_i2h, (const float4*)W_h2h);

    dim3 grid(N_OUT / BN, B_ROWS / BM, 2);   // (12, 128, 2)
    gemm_tc_kernel<<<grid, NTHREADS, SMEM_BYTES>>>(b_i2h, b_h2h);
    epilogue_kernel<<<B_ROWS, 256>>>(hx, out);
}